// round 6
// baseline (speedup 1.0000x reference)
#include <cuda_runtime.h>

#define ATT_H 128
#define KVH   256
#define NB    2
#define NS    1024
#define NQ    512
#define NROWS (NB*NS + NB*NQ)   // 3072 projection rows

// scratch (no allocations allowed)
__device__ float g_proj_kv[NB*NS*ATT_H];   // (B*S, 128)
__device__ float g_proj_q [NB*NQ*ATT_H];   // (B*SQ, 128)
__device__ float g_pp     [2*NROWS*ATT_H]; // proj k-split partials

__device__ __forceinline__ float fast_tanh(float x){ float y; asm("tanh.approx.f32 %0, %1;" : "=f"(y) : "f"(x)); return y; }
__device__ __forceinline__ float fast_ex2 (float x){ float y; asm("ex2.approx.f32 %0, %1;"  : "=f"(y) : "f"(x)); return y; }

__device__ __forceinline__ float2 ffma2(float2 a, float2 b, float2 c) {
    float2 d;
    asm("fma.rn.f32x2 %0, %1, %2, %3;"
        : "=l"(reinterpret_cast<unsigned long long&>(d))
        : "l"(reinterpret_cast<unsigned long long&>(a)),
          "l"(reinterpret_cast<unsigned long long&>(b)),
          "l"(reinterpret_cast<unsigned long long&>(c)));
    return d;
}

__device__ __forceinline__ void cp16(void* dst, const void* src) {
    unsigned d = (unsigned)__cvta_generic_to_shared(dst);
    asm volatile("cp.async.cg.shared.global [%0], [%1], 16;" :: "r"(d), "l"(src));
}
__device__ __forceinline__ void cp_commit() { asm volatile("cp.async.commit_group;"); }
__device__ __forceinline__ void cp_wait0()  { asm volatile("cp.async.wait_group 0;" ::: "memory"); }

// ---------------- Kernel 1: proj partials, k-split x2 ----------------
__global__ void __launch_bounds__(128) proj_kernel(
    const float* __restrict__ kv, const float* __restrict__ qy,
    const float* __restrict__ Wkv, const float* __restrict__ Wq)
{
    __shared__ float w_sh [64*64];
    __shared__ float in_T [64*34];

    const int tid = threadIdx.x;
    const int rb  = blockIdx.x;       // 384 = 96 rowblk * 2 colhalf * 2 khalf
    const int kh  = rb & 1;
    const int ch  = (rb >> 1) & 1;
    const int row0g = (rb >> 2) * 32;

    const float *in, *W;
    if (row0g < NB*NS) { in = kv + (size_t)row0g*256;           W = Wkv; }
    else               { in = qy + (size_t)(row0g - NB*NS)*256; W = Wq;  }
    in += kh*128;
    W  += (size_t)kh*128*128;

    const int tx = tid & 15;
    const int ty = tid >> 4;

    float2 acc[4][2];
    #pragma unroll
    for (int i = 0; i < 4; i++) { acc[i][0] = make_float2(0.f,0.f); acc[i][1] = make_float2(0.f,0.f); }

    float4 wr[8], ir[4];
    #pragma unroll
    for (int j = 0; j < 8; j++) {
        int f4 = tid + 128*j; int kk = f4 >> 4, c4 = f4 & 15;
        wr[j] = *(const float4*)(W + (size_t)kk*128 + ch*64 + c4*4);
    }
    #pragma unroll
    for (int j = 0; j < 4; j++) {
        int f4 = tid + 128*j; int r = f4 >> 4, k4 = f4 & 15;
        ir[j] = *(const float4*)(in + (size_t)r*256 + k4*4);
    }

    for (int kc = 0; kc < 2; kc++) {
        #pragma unroll
        for (int j = 0; j < 8; j++) {
            int f4 = tid + 128*j; int kk = f4 >> 4, c4 = f4 & 15;
            ((float4*)w_sh)[kk*16 + c4] = wr[j];
        }
        #pragma unroll
        for (int j = 0; j < 4; j++) {
            int f4 = tid + 128*j; int r = f4 >> 4, k4 = f4 & 15;
            in_T[(k4*4+0)*34 + r] = ir[j].x;
            in_T[(k4*4+1)*34 + r] = ir[j].y;
            in_T[(k4*4+2)*34 + r] = ir[j].z;
            in_T[(k4*4+3)*34 + r] = ir[j].w;
        }
        __syncthreads();
        if (kc < 1) {
            #pragma unroll
            for (int j = 0; j < 8; j++) {
                int f4 = tid + 128*j; int kk = f4 >> 4, c4 = f4 & 15;
                wr[j] = *(const float4*)(W + (size_t)(64 + kk)*128 + ch*64 + c4*4);
            }
            #pragma unroll
            for (int j = 0; j < 4; j++) {
                int f4 = tid + 128*j; int r = f4 >> 4, k4 = f4 & 15;
                ir[j] = *(const float4*)(in + (size_t)r*256 + 64 + k4*4);
            }
        }
        #pragma unroll 8
        for (int kk = 0; kk < 64; kk++) {
            float4 w4 = ((const float4*)w_sh)[kk*16 + tx];
            float2 i01 = *(const float2*)&in_T[kk*34 + ty*4];
            float2 i23 = *(const float2*)&in_T[kk*34 + ty*4 + 2];
            float iv[4] = {i01.x, i01.y, i23.x, i23.y};
            #pragma unroll
            for (int ri = 0; ri < 4; ri++) {
                float2 ib = make_float2(iv[ri], iv[ri]);
                acc[ri][0] = ffma2(make_float2(w4.x, w4.y), ib, acc[ri][0]);
                acc[ri][1] = ffma2(make_float2(w4.z, w4.w), ib, acc[ri][1]);
            }
        }
        __syncthreads();
    }

    float* outp = g_pp + (size_t)kh*NROWS*ATT_H + (size_t)(row0g + ty*4)*ATT_H + ch*64 + tx*4;
    #pragma unroll
    for (int ri = 0; ri < 4; ri++)
        *(float4*)(outp + (size_t)ri*ATT_H) =
            make_float4(acc[ri][0].x, acc[ri][0].y, acc[ri][1].x, acc[ri][1].y);
}

// ---------------- Kernel 1b: combine proj k-halves + bias ----------------
__global__ void __launch_bounds__(256) proj_fix_kernel(
    const float* __restrict__ bkv, const float* __restrict__ bq)
{
    const int idx = blockIdx.x*256 + threadIdx.x;
    const int row = idx >> 5;
    const int c4  = idx & 31;
    float4 a = ((const float4*)g_pp)[idx];
    float4 b = ((const float4*)g_pp)[idx + NROWS*32];
    const float* bias; float* out; int rloc;
    if (row < NB*NS) { bias = bkv; out = g_proj_kv; rloc = row; }
    else             { bias = bq;  out = g_proj_q;  rloc = row - NB*NS; }
    float4 bb = ((const float4*)bias)[c4];
    float4 o = make_float4(a.x+b.x+bb.x, a.y+b.y+bb.y, a.z+b.z+bb.z, a.w+b.w+bb.w);
    ((float4*)(out + (size_t)rloc*ATT_H))[c4] = o;
}

// ---------------- Kernel 2: FUSED score + softmax + output GEMM ----------------
// Grid 128: one block per (b, 8-q tile). 384 threads:
//   warps 0-7  (256 thr): E producers (tanh scores), MUFU-bound
//   warps 8-11 (128 thr): O accumulators (FFMA2), lag one chunk
// S processed in 32 chunks of 32.
#define CHS    32                       // s per chunk
#define NCH    (NS/CHS)                 // 32 chunks
#define KVBUF  (CHS*KVH)                // 8192 floats per kv buffer
#define PKBUF  (CHS*33*4)               // 4224 floats per pk buffer (pad 33 f4)
#define SM_FLOATS (3*KVBUF + 2*PKBUF + 2*256 + 8*33*4 + 128 + 64 + 8)

__global__ void __launch_bounds__(384) fused_kernel(
    const float* __restrict__ kv_g, const float* __restrict__ wv_g,
    const float* __restrict__ bv_g,
    float* __restrict__ out_o, float* __restrict__ out_w)
{
    extern __shared__ float sm[];
    float* kv_buf = sm;                       // 3 * 8192
    float* pk_buf = kv_buf + 3*KVBUF;         // 2 * 4224
    float* E_ch   = pk_buf + 2*PKBUF;         // 2 * 256
    float* pq_sh  = E_ch   + 512;             // 8 * 33 * 4 = 1056
    float* wv_sh  = pq_sh  + 1056;            // 128
    float* red    = wv_sh  + 128;             // 64
    float* inv_sh = red    + 64;              // 8

    const int tid = threadIdx.x;
    const int bid = blockIdx.x;               // 128 = 2 b * 64 q-tiles
    const int b   = bid >> 6;
    const int q0  = (bid & 63) * 8;

    // ---- cp.async issue for chunk c (pk by E-threads, kv by GEMM threads) ----
    #define ISSUE(c)                                                          \
    {                                                                         \
        if (tid < 256) {                                                      \
            int r = tid >> 3, o = tid & 7;                                    \
            const float* src = g_proj_kv + ((size_t)(b*NS) + (c)*CHS + r)*128;\
            float* dst = pk_buf + ((c)&1)*PKBUF + r*132;                      \
            _Pragma("unroll")                                                 \
            for (int j = 0; j < 4; j++)                                       \
                cp16(dst + (o + 8*j)*4, src + (o + 8*j)*4);                   \
        } else {                                                              \
            int t = tid - 256; int s = t >> 2, c4 = t & 3;                    \
            const float* src = kv_g + ((size_t)(b*NS) + (c)*CHS + s)*KVH;     \
            float* dst = kv_buf + ((c)%3)*KVBUF + s*KVH;                      \
            _Pragma("unroll")                                                 \
            for (int j = 0; j < 16; j++)                                      \
                cp16(dst + (c4 + 4*j)*4, src + (c4 + 4*j)*4);                 \
        }                                                                     \
    }

    // prologue: pq, wv, and chunk-0 stage
    if (tid < 256) {
        int q = tid >> 5, a4 = tid & 31;
        ((float4*)pq_sh)[q*33 + a4] =
            *(const float4*)(g_proj_q + (size_t)(b*NQ + q0 + q)*ATT_H + a4*4);
    } else if (tid < 288) {
        ((float4*)wv_sh)[tid - 256] = ((const float4*)wv_g)[tid - 256];
    }
    ISSUE(0);
    cp_commit();

    const float bv = __ldg(bv_g);

    // E-thread identity
    const int lane = tid & 31;
    const int w    = tid >> 5;          // warp id
    const int sl   = (w << 2) + (lane >> 3);  // s within chunk (E-threads)
    const int qq   = lane & 7;                // q (E-threads)
    float rsum = 0.f;

    // GEMM-thread identity
    const int gt = tid - 256;           // 0..127 (valid for warps 8-11)
    float2 oacc[8];
    #pragma unroll
    for (int i = 0; i < 8; i++) oacc[i] = make_float2(0.f, 0.f);

    for (int c = 0; c < NCH; c++) {
        cp_wait0();
        __syncthreads();
        if (c + 1 < NCH) ISSUE(c + 1);
        cp_commit();

        if (tid < 256) {
            // ---- E producer: score chunk c ----
            const float4* pkrow = (const float4*)(pk_buf + (c&1)*PKBUF) + sl*33;
            const float4* pqrow = (const float4*)pq_sh + qq*33;
            const float4* wvr   = (const float4*)wv_sh;
            float acc = 0.f;
            #pragma unroll
            for (int a4 = 0; a4 < 32; a4++) {
                float4 pk = pkrow[a4];
                float4 pq = pqrow[a4];
                float4 wv = wvr[a4];
                acc += wv.x * fast_tanh(pk.x + pq.x);
                acc += wv.y * fast_tanh(pk.y + pq.y);
                acc += wv.z * fast_tanh(pk.z + pq.z);
                acc += wv.w * fast_tanh(pk.w + pq.w);
            }
            float E = fast_ex2((acc + bv) * 1.44269504f);
            rsum += E;
            E_ch[(c&1)*256 + sl*8 + qq] = E;
        } else if (c > 0) {
            // ---- GEMM consumer: chunk c-1 ----
            const int m = c - 1;
            const float* kvb = kv_buf + (m%3)*KVBUF;
            const float* Eb  = E_ch + (m&1)*256;
            #pragma unroll 8
            for (int s = 0; s < CHS; s++) {
                float4 e03 = ((const float4*)Eb)[s*2];
                float4 e47 = ((const float4*)Eb)[s*2 + 1];
                float2 k2  = *(const float2*)(kvb + s*KVH + gt*2);
                oacc[0] = ffma2(k2, make_float2(e03.x, e03.x), oacc[0]);
                oacc[1] = ffma2(k2, make_float2(e03.y, e03.y), oacc[1]);
                oacc[2] = ffma2(k2, make_float2(e03.z, e03.z), oacc[2]);
                oacc[3] = ffma2(k2, make_float2(e03.w, e03.w), oacc[3]);
                oacc[4] = ffma2(k2, make_float2(e47.x, e47.x), oacc[4]);
                oacc[5] = ffma2(k2, make_float2(e47.y, e47.y), oacc[5]);
                oacc[6] = ffma2(k2, make_float2(e47.z, e47.z), oacc[6]);
                oacc[7] = ffma2(k2, make_float2(e47.w, e47.w), oacc[7]);
            }
            // stream raw E of chunk m to out_w (coalesced float2)
            int qr = gt >> 4, s2 = (gt & 15) * 2;
            float2 ev = make_float2(Eb[s2*8 + qr], Eb[(s2+1)*8 + qr]);
            *(float2*)(out_w + (size_t)(b*NQ + q0 + qr)*NS + m*CHS + s2) = ev;
        }
    }

    // drain: GEMM consumes chunk 31
    __syncthreads();
    if (tid >= 256) {
        const int m = NCH - 1;
        const float* kvb = kv_buf + (m%3)*KVBUF;
        const float* Eb  = E_ch + (m&1)*256;
        #pragma unroll 8
        for (int s = 0; s < CHS; s++) {
            float4 e03 = ((const float4*)Eb)[s*2];
            float4 e47 = ((const float4*)Eb)[s*2 + 1];
            float2 k2  = *(const float2*)(kvb + s*KVH + gt*2);
            oacc[0] = ffma2(k2, make_float2(e03.x, e03.x), oacc[0]);
            oacc[1] = ffma2(k2, make_float2(e03.y, e03.y), oacc[1]);
            oacc[2] = ffma2(k2, make_float2(e03.z, e03.z), oacc[2]);
            oacc[3] = ffma2(k2, make_float2(e03.w, e03.w), oacc[3]);
            oacc[4] = ffma2(k2, make_float2(e47.x, e47.x), oacc[4]);
            oacc[5] = ffma2(k2, make_float2(e47.y, e47.y), oacc[5]);
            oacc[6] = ffma2(k2, make_float2(e47.z, e47.z), oacc[6]);
            oacc[7] = ffma2(k2, make_float2(e47.w, e47.w), oacc[7]);
        }
        int qr = gt >> 4, s2 = (gt & 15) * 2;
        float2 ev = make_float2(Eb[s2*8 + qr], Eb[(s2+1)*8 + qr]);
        *(float2*)(out_w + (size_t)(b*NQ + q0 + qr)*NS + m*CHS + s2) = ev;
    } else {
        // rowsum reduce: lanes {l, l^8, l^16, l^24} share q = l&7
        rsum += __shfl_xor_sync(0xffffffffu, rsum, 8);
        rsum += __shfl_xor_sync(0xffffffffu, rsum, 16);
        if (lane < 8) red[w*8 + lane] = rsum;
    }
    __syncthreads();
    if (tid < 8) {
        float s = 0.f;
        #pragma unroll
        for (int ww = 0; ww < 8; ww++) s += red[ww*8 + tid];
        inv_sh[tid] = 1.0f / s;
    }
    __syncthreads();

    // epilogue: normalized attention_output
    if (tid >= 256) {
        #pragma unroll
        for (int q = 0; q < 8; q++) {
            float inv = inv_sh[q];
            *(float2*)(out_o + (size_t)(b*NQ + q0 + q)*KVH + gt*2) =
                make_float2(oacc[q].x * inv, oacc[q].y * inv);
        }
    }
    // epilogue: rescale this block's out_w rows in place (L2-hot)
    {
        float4* Wb = (float4*)(out_w + (size_t)(b*NQ + q0)*NS);
        for (int idx = tid; idx < 8*NS/4; idx += 384) {
            float inv = inv_sh[idx >> 8];
            float4 v = Wb[idx];
            v.x *= inv; v.y *= inv; v.z *= inv; v.w *= inv;
            Wb[idx] = v;
        }
    }
    #undef ISSUE
}

extern "C" void kernel_launch(void* const* d_in, const int* in_sizes, int n_in,
                              void* d_out, int out_size)
{
    const float* kv  = (const float*)d_in[0];   // (2,1024,256)
    const float* qy  = (const float*)d_in[1];   // (2,512,256)
    const float* Wkv = (const float*)d_in[2];   // (256,128)
    const float* bkv = (const float*)d_in[3];   // (128)
    const float* Wq  = (const float*)d_in[4];   // (256,128)
    const float* bq  = (const float*)d_in[5];   // (128)
    const float* wv  = (const float*)d_in[6];   // (128)
    const float* bv  = (const float*)d_in[7];   // scalar

    float* out_o = (float*)d_out;               // attention_output: 2*512*256
    float* out_w = out_o + NB*NQ*KVH;           // attention_weight: 2*512*1024

    static int smem_set = 0;
    const int smem_bytes = SM_FLOATS * 4;
    if (!smem_set) {
        cudaFuncSetAttribute(fused_kernel, cudaFuncAttributeMaxDynamicSharedMemorySize, smem_bytes);
        smem_set = 1;
    }

    proj_kernel    <<<384, 128>>>(kv, qy, Wkv, Wq);
    proj_fix_kernel<<<384, 256>>>(bkv, bq);
    fused_kernel   <<<128, 384, smem_bytes>>>(kv, wv, bv, out_o, out_w);
}